// round 17
// baseline (speedup 1.0000x reference)
#include <cuda_runtime.h>
#include <cstdint>

#define NUM_SMS      152
#define CTAS_PER_SM  4
#define NUM_BLOCKS   (NUM_SMS * CTAS_PER_SM)   // 608 total
#define KEEP_BLOCKS  304                        // blocks serving the L2-resident half
#define STREAM_BLOCKS (NUM_BLOCKS - KEEP_BLOCKS)
#define NUM_THREADS  512

// Resident float4s per array: 3 * 2M * 16B = 96 MB pinned in L2
// (measured: fully resident at 96 MB; cliff starts just above).
#define RESIDENT_F4 (2u * 1024u * 1024u)

// Self-resetting cross-launch state (graph-replay safe, no init kernel):
__device__ float        g_sum;
__device__ unsigned int g_cnt;
__device__ unsigned int g_ticket;

__device__ __forceinline__ uint64_t make_policy_keep() {
    uint64_t pol;
    asm("createpolicy.fractional.L2::evict_last.b64 %0, 1.0;" : "=l"(pol));
    return pol;
}
__device__ __forceinline__ uint64_t make_policy_stream() {
    uint64_t pol;
    asm("createpolicy.fractional.L2::evict_first.b64 %0, 1.0;" : "=l"(pol));
    return pol;
}

__device__ __forceinline__ float4 ldg_hint(const float4* p, uint64_t pol) {
    float4 r;
    asm volatile("ld.global.nc.L2::cache_hint.v4.f32 {%0,%1,%2,%3}, [%4], %5;"
        : "=f"(r.x), "=f"(r.y), "=f"(r.z), "=f"(r.w)
        : "l"(p), "l"(pol));
    return r;
}

// Shared 2x-unrolled accumulation over [lo, hi) with the given stride/policy.
__device__ __forceinline__ void accum_range(
    const float4* __restrict__ out,
    const float4* __restrict__ lbl0,
    const float4* __restrict__ lbl1,
    int i, int hi, int stride, uint64_t pol,
    float& acc, unsigned int& cnt)
{
    for (; i + stride < hi; i += 2 * stride) {
        float4 o0 = ldg_hint(out  + i, pol);
        float4 a0 = ldg_hint(lbl0 + i, pol);
        float4 b0 = ldg_hint(lbl1 + i, pol);
        float4 o1 = ldg_hint(out  + i + stride, pol);
        float4 a1 = ldg_hint(lbl0 + i + stride, pol);
        float4 b1 = ldg_hint(lbl1 + i + stride, pol);

        acc += fabsf(o0.x - a0.x) * b0.x;
        acc += fabsf(o0.y - a0.y) * b0.y;
        acc += fabsf(o0.z - a0.z) * b0.z;
        acc += fabsf(o0.w - a0.w) * b0.w;
        acc += fabsf(o1.x - a1.x) * b1.x;
        acc += fabsf(o1.y - a1.y) * b1.y;
        acc += fabsf(o1.z - a1.z) * b1.z;
        acc += fabsf(o1.w - a1.w) * b1.w;

        cnt += (a0.x != 0.0f) + (a0.y != 0.0f) + (a0.z != 0.0f) + (a0.w != 0.0f);
        cnt += (a1.x != 0.0f) + (a1.y != 0.0f) + (a1.z != 0.0f) + (a1.w != 0.0f);
    }
    for (; i < hi; i += stride) {
        float4 o = ldg_hint(out  + i, pol);
        float4 a = ldg_hint(lbl0 + i, pol);
        float4 b = ldg_hint(lbl1 + i, pol);
        acc += fabsf(o.x - a.x) * b.x;
        acc += fabsf(o.y - a.y) * b.y;
        acc += fabsf(o.z - a.z) * b.z;
        acc += fabsf(o.w - a.w) * b.w;
        cnt += (a.x != 0.0f) + (a.y != 0.0f) + (a.z != 0.0f) + (a.w != 0.0f);
    }
}

__global__ void __launch_bounds__(NUM_THREADS, CTAS_PER_SM) dlwm_fused_kernel(
    const float4* __restrict__ out,
    const float4* __restrict__ lbl0,
    const float4* __restrict__ lbl1,
    float* __restrict__ d_out,
    int n4, int split4)
{
    float acc = 0.0f;
    unsigned int cnt = 0;

    // Block-level phase partition: L2-hit blocks and DRAM-stream blocks run
    // CONCURRENTLY, each devoting all of its in-flight load slots to its own
    // memory resource (instruction-level interleave starved DRAM — R13).
    if (blockIdx.x < KEEP_BLOCKS) {
        const uint64_t pol = make_policy_keep();
        const int stride = KEEP_BLOCKS * NUM_THREADS;
        const int i0 = blockIdx.x * NUM_THREADS + threadIdx.x;
        accum_range(out, lbl0, lbl1, i0, split4, stride, pol, acc, cnt);
    } else {
        const uint64_t pol = make_policy_stream();
        const int stride = STREAM_BLOCKS * NUM_THREADS;
        const int i0 = split4 + (blockIdx.x - KEEP_BLOCKS) * NUM_THREADS + threadIdx.x;
        accum_range(out, lbl0, lbl1, i0, n4, stride, pol, acc, cnt);
    }

    // ---- intra-block reduction ----
    cnt = __reduce_add_sync(0xFFFFFFFFu, cnt);
    #pragma unroll
    for (int off = 16; off > 0; off >>= 1)
        acc += __shfl_down_sync(0xFFFFFFFFu, acc, off);

    __shared__ float        s_acc[NUM_THREADS / 32];
    __shared__ unsigned int s_cnt[NUM_THREADS / 32];
    const int lane = threadIdx.x & 31;
    const int wid  = threadIdx.x >> 5;
    if (lane == 0) { s_acc[wid] = acc; s_cnt[wid] = cnt; }
    __syncthreads();

    if (wid == 0) {
        acc = (lane < (NUM_THREADS / 32)) ? s_acc[lane] : 0.0f;
        cnt = (lane < (NUM_THREADS / 32)) ? s_cnt[lane] : 0u;
        cnt = __reduce_add_sync(0xFFFFFFFFu, cnt);
        #pragma unroll
        for (int off = 8; off > 0; off >>= 1)
            acc += __shfl_down_sync(0xFFFFFFFFu, acc, off);

        if (lane == 0) {
            atomicAdd(&g_sum, acc);
            atomicAdd(&g_cnt, cnt);

            unsigned int ticket;
            asm volatile(
                "atom.acq_rel.gpu.global.add.u32 %0, [%1], %2;"
                : "=r"(ticket)
                : "l"(&g_ticket), "r"(1u)
                : "memory");

            if (ticket == gridDim.x - 1) {
                float        fsum = atomicExch(&g_sum, 0.0f);
                unsigned int csum = atomicExch(&g_cnt, 0u);
                d_out[0] = (csum == 0u) ? 0.0f : (fsum / (float)csum);
                atomicExch(&g_ticket, 0u);
            }
        }
    }
}

extern "C" void kernel_launch(void* const* d_in, const int* in_sizes, int n_in,
                              void* d_out, int out_size)
{
    const float4* out_t = (const float4*)d_in[0];
    const float4* lbl0  = (const float4*)d_in[1];
    const float4* lbl1  = (const float4*)d_in[2];
    const int n  = in_sizes[0];   // 15,728,640 (divisible by 4)
    const int n4 = n >> 2;        // 3,932,160

    int split4 = (int)RESIDENT_F4;
    if (split4 > n4) split4 = n4;

    dlwm_fused_kernel<<<NUM_BLOCKS, NUM_THREADS>>>(out_t, lbl0, lbl1,
                                                   (float*)d_out, n4, split4);
}